// round 6
// baseline (speedup 1.0000x reference)
#include <cuda_runtime.h>
#include <cuda_fp16.h>
#include <stdint.h>
#include <math.h>

#define EPSF 1e-8f
#define DD 128               // d
#define KPAD 10048           // 628*16 padded K (= problem N)
#define NCHUNKS 157          // 64-k chunks
#define EPAD 5120
#define EPITCH 5120
#define NKS 4                // K splits

// ---------------- static device scratch (no allocation) ----------------------
static __device__ __align__(256) __half g_FsT[DD * KPAD];          // Fs^T K-major f16
static __device__ __align__(256) float g_Mpart[NKS * DD * EPITCH]; // 10.5 MB partials
static __device__ float g_deinv[EPAD];
static __device__ float g_blocksum[2560];
static __device__ float g_f2sum[640];
static __device__ int   g_count;

// ---------------- helpers ----------------------------------------------------
__device__ __forceinline__ uint32_t smem_u32(const void* p) {
    uint32_t a;
    asm("{ .reg .u64 t; cvta.to.shared.u64 t, %1; cvt.u32.u64 %0, t; }"
        : "=r"(a) : "l"(p));
    return a;
}
#define SWZ(o) ((o) ^ (((o) >> 3) & 0x70))

__device__ __forceinline__ void sts128(uint32_t addr, uint32_t a, uint32_t b,
                                       uint32_t c, uint32_t d) {
    asm volatile("st.shared.v4.b32 [%0], {%1,%2,%3,%4};"
                 :: "r"(addr), "r"(a), "r"(b), "r"(c), "r"(d) : "memory");
}
#define CPA16(dst, src) \
    asm volatile("cp.async.ca.shared.global [%0], [%1], 16;" \
                 :: "r"(dst), "l"(src) : "memory")
#define CPA_COMMIT() asm volatile("cp.async.commit_group;" ::: "memory")
#define CPA_WAIT0()  asm volatile("cp.async.wait_group 0;" ::: "memory")

#define LDSM4(r, addr) \
    asm volatile("ldmatrix.sync.aligned.m8n8.x4.shared.b16 {%0,%1,%2,%3}, [%4];" \
                 : "=r"((r)[0]), "=r"((r)[1]), "=r"((r)[2]), "=r"((r)[3]) : "r"(addr))
#define LDSM4T(r, addr) \
    asm volatile("ldmatrix.sync.aligned.m8n8.x4.trans.shared.b16 {%0,%1,%2,%3}, [%4];" \
                 : "=r"((r)[0]), "=r"((r)[1]), "=r"((r)[2]), "=r"((r)[3]) : "r"(addr))

// f16-accumulate MMA: D,C are 2 regs (4 f16), A 4 regs, B 2 regs.
__device__ __forceinline__ void mma16816_h(uint32_t* c, const uint32_t* a,
                                           uint32_t b0, uint32_t b1) {
    asm volatile(
        "mma.sync.aligned.m16n8k16.row.col.f16.f16.f16.f16 "
        "{%0,%1}, {%2,%3,%4,%5}, {%6,%7}, {%0,%1};"
        : "+r"(c[0]), "+r"(c[1])
        : "r"(a[0]), "r"(a[1]), "r"(a[2]), "r"(a[3]), "r"(b0), "r"(b1));
}

// ---------------- prep: FsT transpose (f16) + sum(F^2) + deinv ---------------
__global__ void __launch_bounds__(256, 4)
prep_fst(const float* __restrict__ F, const float* __restrict__ Dv,
         const float* __restrict__ De, int Nn, int Ee) {
    __shared__ __half s[16][132];
    __shared__ float red[256];
    __shared__ float dvis[16];
    const int t = threadIdx.x;
    const int n0 = blockIdx.x * 16;

    if (t < 16) {
        int n = n0 + t;
        dvis[t] = (n < Nn) ? rsqrtf(Dv[(size_t)n * Nn + n] + EPSF) : 0.f;
    }
    if (blockIdx.x < 20) {
        int e = blockIdx.x * 256 + t;
        g_deinv[e] = (e < Ee) ? 1.f / (De[(size_t)e * Ee + e] + EPSF) : 0.f;
    }
    __syncthreads();

    float f2 = 0.f;
    #pragma unroll
    for (int i = 0; i < 2; ++i) {
        int g = t + 256 * i;
        int nl = g >> 5;
        int d4 = (g & 31) * 4;
        int n = n0 + nl;
        float4 v = make_float4(0.f, 0.f, 0.f, 0.f);
        float sc = 0.f;
        if (n < Nn) { v = *(const float4*)&F[(size_t)n * DD + d4]; sc = dvis[nl]; }
        f2 += v.x * v.x + v.y * v.y + v.z * v.z + v.w * v.w;
        s[nl][d4 + 0] = __float2half(v.x * sc);
        s[nl][d4 + 1] = __float2half(v.y * sc);
        s[nl][d4 + 2] = __float2half(v.z * sc);
        s[nl][d4 + 3] = __float2half(v.w * sc);
    }
    __syncthreads();
    {
        int d = t >> 1;
        int nh = (t & 1) * 8;
        uint32_t w[4];
        #pragma unroll
        for (int j = 0; j < 4; ++j) {
            __half2 p;
            p.x = s[nh + 2 * j][d];
            p.y = s[nh + 2 * j + 1][d];
            w[j] = *(uint32_t*)&p;
        }
        *(uint4*)&g_FsT[(size_t)d * KPAD + n0 + nh] = make_uint4(w[0], w[1], w[2], w[3]);
    }
    red[t] = f2;
    __syncthreads();
    #pragma unroll
    for (int s2 = 128; s2 > 0; s2 >>= 1) {
        if (t < s2) red[t] += red[t + s2];
        __syncthreads();
    }
    if (t == 0) g_f2sum[blockIdx.x] = red[0];
}

// ---------------- GEMM: mma.sync f16-acc, CTA 128(d) x 64(e), occ 2 ----------
// Static SMEM 48KB: A 2x16KB @0, B 2x8KB @32768.
__global__ void __launch_bounds__(256, 2)
gemm_kernel(const float* __restrict__ H, int Nn, int Ee) {
    __shared__ __align__(1024) char smem[49152];
    const uint32_t sb = smem_u32(smem);

    const int t = threadIdx.x;
    const int lane = t & 31;
    const int wid = t >> 5;
    const int wm = wid & 3;            // 4 m-warps (32 d each)
    const int wn = wid >> 2;           // 2 n-warps (32 e each)
    const int m0 = wm * 32;
    const int n0w = wn * 32;

    const int et = blockIdx.x;
    const int sl = blockIdx.y;
    const int e0 = et * 64;
    const int c0 = (sl * NCHUNKS) / NKS;
    const int c1 = ((sl + 1) * NCHUNKS) / NKS;
    const int nch = c1 - c0;
    const bool tail = (e0 + 64 > Ee);

    const int krow = t >> 2;           // 0..63
    const int ecol = (t & 3) * 16;     // 16 e per thread

    uint32_t hacc[2][4][2];            // f16x2 accumulators
    float sh[2][4][4];                 // f32 shadows
    #pragma unroll
    for (int i = 0; i < 2; ++i)
        #pragma unroll
        for (int j = 0; j < 4; ++j) {
            hacc[i][j][0] = 0u; hacc[i][j][1] = 0u;
            #pragma unroll
            for (int q = 0; q < 4; ++q) sh[i][j][q] = 0.f;
        }

    const int aRow = (lane & 15);
    const int aKh  = (lane >> 4) * 8;
    const int bKr  = (lane & 15);
    const int bNc  = (lane >> 4) * 8;

    uint32_t w[8];                     // converted B staging (f16x2)

#define LOAD_A(buf, chunk) do {                                              \
        int _cg = (chunk);                                                   \
        _Pragma("unroll")                                                    \
        for (int _i = 0; _i < 4; ++_i) {                                     \
            int pos = t + 256 * _i;                                          \
            int row = pos >> 3;                                              \
            int cc2 = pos & 7;                                               \
            const __half* src = &g_FsT[(size_t)row * KPAD + _cg * 64 + cc2 * 8]; \
            uint32_t off = (uint32_t)(row * 128 + cc2 * 16);                 \
            CPA16((buf) + SWZ(off), src);                                    \
        }                                                                    \
    } while (0)

#define LDG_H(chunk) do {                                                    \
        int _n = (chunk) * 64 + krow;                                        \
        bool _v = _n < Nn;                                                   \
        const float* _hr = H + (size_t)_n * Ee;                              \
        _Pragma("unroll")                                                    \
        for (int _j = 0; _j < 4; ++_j) {                                     \
            float4 f;                                                        \
            if (!tail) {                                                     \
                f = _v ? *(const float4*)&_hr[e0 + ecol + 4 * _j]            \
                       : make_float4(0.f, 0.f, 0.f, 0.f);                    \
            } else {                                                         \
                int _e = e0 + ecol + 4 * _j;                                 \
                f.x = (_v && _e + 0 < Ee) ? _hr[_e + 0] : 0.f;               \
                f.y = (_v && _e + 1 < Ee) ? _hr[_e + 1] : 0.f;               \
                f.z = (_v && _e + 2 < Ee) ? _hr[_e + 2] : 0.f;               \
                f.w = (_v && _e + 3 < Ee) ? _hr[_e + 3] : 0.f;               \
            }                                                                \
            __half2 p0 = __floats2half2_rn(f.x, f.y);                        \
            __half2 p1 = __floats2half2_rn(f.z, f.w);                        \
            w[2 * _j]     = *(uint32_t*)&p0;                                 \
            w[2 * _j + 1] = *(uint32_t*)&p1;                                 \
        }                                                                    \
    } while (0)

#define STS_H(buf) do {                                                      \
        uint32_t off = (uint32_t)(krow * 128 + ecol * 2);                    \
        sts128((buf) + SWZ(off),      w[0], w[1], w[2], w[3]);               \
        sts128((buf) + SWZ(off + 16), w[4], w[5], w[6], w[7]);               \
    } while (0)

#define COMPUTE(abuf, bbuf) do {                                             \
        _Pragma("unroll")                                                    \
        for (int k0 = 0; k0 < 64; k0 += 16) {                                \
            uint32_t afr[2][4];                                              \
            _Pragma("unroll")                                                \
            for (int i = 0; i < 2; ++i) {                                    \
                uint32_t off = (uint32_t)((m0 + i * 16 + aRow) * 128         \
                                          + (k0 + aKh) * 2);                 \
                LDSM4(afr[i], (abuf) + SWZ(off));                            \
            }                                                                \
            uint32_t bfr[2][4];                                              \
            _Pragma("unroll")                                                \
            for (int jb = 0; jb < 2; ++jb) {                                 \
                uint32_t off = (uint32_t)((k0 + bKr) * 128                   \
                                          + (n0w + jb * 16 + bNc) * 2);      \
                LDSM4T(bfr[jb], (bbuf) + SWZ(off));                          \
            }                                                                \
            _Pragma("unroll")                                                \
            for (int i = 0; i < 2; ++i)                                      \
                _Pragma("unroll")                                            \
                for (int j = 0; j < 4; ++j)                                  \
                    mma16816_h(hacc[i][j], afr[i],                           \
                               bfr[j >> 1][(j & 1) * 2],                     \
                               bfr[j >> 1][(j & 1) * 2 + 1]);                \
        }                                                                    \
    } while (0)

#define PROMOTE() do {                                                       \
        _Pragma("unroll")                                                    \
        for (int i = 0; i < 2; ++i)                                          \
            _Pragma("unroll")                                                \
            for (int j = 0; j < 4; ++j) {                                    \
                float2 lo = __half22float2(*(__half2*)&hacc[i][j][0]);       \
                float2 hi = __half22float2(*(__half2*)&hacc[i][j][1]);       \
                sh[i][j][0] += lo.x; sh[i][j][1] += lo.y;                    \
                sh[i][j][2] += hi.x; sh[i][j][3] += hi.y;                    \
                hacc[i][j][0] = 0u;  hacc[i][j][1] = 0u;                     \
            }                                                                \
    } while (0)

    // ---- pipeline (double-buffered) ----
    LOAD_A(sb, c0);
    CPA_COMMIT();
    LDG_H(c0);
    CPA_WAIT0();
    STS_H(sb + 32768);
    __syncthreads();

    for (int cc = 0; cc < nch; ++cc) {
        const int b = cc & 1;
        const uint32_t aCur = sb + b * 16384;
        const uint32_t bCur = sb + 32768 + b * 8192;
        const uint32_t aNxt = sb + (b ^ 1) * 16384;
        const uint32_t bNxt = sb + 32768 + (b ^ 1) * 8192;
        const bool has = (cc + 1) < nch;
        if (has) {
            LOAD_A(aNxt, c0 + cc + 1);
            CPA_COMMIT();
            LDG_H(c0 + cc + 1);
        }
        COMPUTE(aCur, bCur);
        if ((cc & 1) || (cc == nch - 1)) PROMOTE();
        if (has) {
            CPA_WAIT0();
            STS_H(bNxt);
        }
        __syncthreads();
    }

    // ---- write partials: g_Mpart[sl][d][e] ----
    #pragma unroll
    for (int i = 0; i < 2; ++i) {
        #pragma unroll
        for (int j = 0; j < 4; ++j) {
            int d = m0 + i * 16 + (lane >> 2);
            int e = e0 + n0w + j * 8 + (lane & 3) * 2;
            size_t base = ((size_t)(sl * DD + d)) * EPITCH + e;
            *(float2*)&g_Mpart[base] = make_float2(sh[i][j][0], sh[i][j][1]);
            *(float2*)&g_Mpart[base + (size_t)8 * EPITCH] =
                make_float2(sh[i][j][2], sh[i][j][3]);
        }
    }
}

// ---------------- pass 3 + fused final reduce --------------------------------
// grid 2560: d = bid/20, e = (bid%20)*256 + t. Last block does the final sum.
__global__ void __launch_bounds__(256, 8)
pass3_kernel(float* __restrict__ out, int Nn, int nprep) {
    __shared__ float r[256];
    __shared__ int isLast;
    const int t = threadIdx.x;
    const int d = blockIdx.x / 20;
    const int e = (blockIdx.x % 20) * 256 + t;
    float v = 0.f;
    #pragma unroll
    for (int j = 0; j < NKS; ++j)
        v += g_Mpart[((size_t)(j * DD + d)) * EPITCH + e];
    r[t] = v * v * g_deinv[e];
    __syncthreads();
    #pragma unroll
    for (int s = 128; s > 0; s >>= 1) {
        if (t < s) r[t] += r[t + s];
        __syncthreads();
    }
    if (t == 0) {
        g_blocksum[blockIdx.x] = r[0];
        __threadfence();
        int done = atomicAdd(&g_count, 1);
        isLast = (done == (int)gridDim.x - 1);
    }
    __syncthreads();
    if (isLast) {
        float acc = 0.f;
        for (int i = t; i < nprep; i += 256) acc += g_f2sum[i];
        for (int i = t; i < 2560; i += 256) acc -= g_blocksum[i];
        r[t] = acc;
        __syncthreads();
        #pragma unroll
        for (int s = 128; s > 0; s >>= 1) {
            if (t < s) r[t] += r[t + s];
            __syncthreads();
        }
        if (t == 0) {
            out[0] = r[0] / (float)Nn;
            g_count = 0;               // reset for next replay
        }
    }
}

// ---------------- launch ------------------------------------------------------
extern "C" void kernel_launch(void* const* d_in, const int* in_sizes, int n_in,
                              void* d_out, int out_size) {
    const float* F  = (const float*)d_in[0];   // [N,128]
    const float* H  = (const float*)d_in[1];   // [N,E]
    const float* Dv = (const float*)d_in[2];   // [N,N]
    const float* De = (const float*)d_in[3];   // [E,E]
    float* out = (float*)d_out;

    int Nn = in_sizes[0] / DD;                 // 10000
    int Ee = in_sizes[1] / Nn;                 // 5000
    int etiles = (Ee + 63) / 64;               // 79
    int nprep = KPAD / 16;                     // 628

    prep_fst<<<nprep, 256>>>(F, Dv, De, Nn, Ee);
    gemm_kernel<<<dim3(etiles, NKS), 256>>>(H, Nn, Ee);
    pass3_kernel<<<2560, 256>>>(out, Nn, nprep);
}

// round 7
// speedup vs baseline: 1.0455x; 1.0455x over previous
#include <cuda_runtime.h>
#include <cuda_bf16.h>
#include <stdint.h>
#include <math.h>

#define EPSF 1e-8f
#define DD 128               // d
#define NCHUNKS 157          // 64-k chunks
#define NPAD (NCHUNKS * 64)  // 10048
#define EPAD 5120
#define EPITCH 5120
#define ETILE 72             // 64 HMMA + 8 SIMT
#define NSLMAX 5

// ---------------- static device scratch (no allocation) ----------------------
static __device__ __align__(256) __nv_bfloat16 g_Fs[NPAD * DD];      // row-major bf16
static __device__ __align__(256) float g_Mpart[NSLMAX * DD * EPITCH]; // 13.1 MB
static __device__ float g_deinv[EPAD];
static __device__ float g_blocksum[2560];
static __device__ float g_f2sum[256];
static __device__ int   g_count;

// ---------------- helpers ----------------------------------------------------
__device__ __forceinline__ uint32_t smem_u32(const void* p) {
    uint32_t a;
    asm("{ .reg .u64 t; cvta.to.shared.u64 t, %1; cvt.u32.u64 %0, t; }"
        : "=r"(a) : "l"(p));
    return a;
}
#define SWZ(o)    ((o) ^ (((o) >> 3) & 0x70))   // 128B-pitch tiles (B)
#define SWZ256(o) ((o) ^ (((o) >> 4) & 0x70))   // 256B-pitch tiles (A)

__device__ __forceinline__ void sts128(uint32_t addr, uint32_t a, uint32_t b,
                                       uint32_t c, uint32_t d) {
    asm volatile("st.shared.v4.b32 [%0], {%1,%2,%3,%4};"
                 :: "r"(addr), "r"(a), "r"(b), "r"(c), "r"(d) : "memory");
}
#define CPA16(dst, src) \
    asm volatile("cp.async.ca.shared.global [%0], [%1], 16;" \
                 :: "r"(dst), "l"(src) : "memory")
#define CPA_COMMIT() asm volatile("cp.async.commit_group;" ::: "memory")
#define CPA_WAIT0()  asm volatile("cp.async.wait_group 0;" ::: "memory")

// B fragments: [k][n] tile, 128B pitch
#define LDSM4T(r, addr) \
    asm volatile("ldmatrix.sync.aligned.m8n8.x4.trans.shared.b16 {%0,%1,%2,%3}, [%4];" \
                 : "=r"((r)[0]), "=r"((r)[1]), "=r"((r)[2]), "=r"((r)[3]) : "r"(addr))
// A fragments from [k][m] tile: permuted outputs so r = (a0,a1,a2,a3)
#define LDSM4T_A(r, addr) \
    asm volatile("ldmatrix.sync.aligned.m8n8.x4.trans.shared.b16 {%0,%1,%2,%3}, [%4];" \
                 : "=r"((r)[0]), "=r"((r)[2]), "=r"((r)[1]), "=r"((r)[3]) : "r"(addr))

__device__ __forceinline__ void mma16816(float* c, const uint32_t* a,
                                         uint32_t b0, uint32_t b1) {
    asm volatile(
        "mma.sync.aligned.m16n8k16.row.col.f32.bf16.bf16.f32 "
        "{%0,%1,%2,%3}, {%4,%5,%6,%7}, {%8,%9}, {%0,%1,%2,%3};"
        : "+f"(c[0]), "+f"(c[1]), "+f"(c[2]), "+f"(c[3])
        : "r"(a[0]), "r"(a[1]), "r"(a[2]), "r"(a[3]), "r"(b0), "r"(b1));
}

// f32x2 SIMT helpers
typedef unsigned long long ull;
__device__ __forceinline__ ull pack2u(uint32_t lo, uint32_t hi) {
    ull r; asm("mov.b64 %0, {%1,%2};" : "=l"(r) : "r"(lo), "r"(hi)); return r;
}
__device__ __forceinline__ void unpack2f(ull v, float& lo, float& hi) {
    asm("mov.b64 {%0,%1}, %2;" : "=f"(lo), "=f"(hi) : "l"(v));
}
__device__ __forceinline__ ull ffma2(ull a, ull b, ull c) {
    ull d; asm("fma.rn.f32x2 %0, %1, %2, %3;" : "=l"(d) : "l"(a), "l"(b), "l"(c));
    return d;
}

// ---------------- prep: Fs = F * dvis (bf16, row-major) + sum(F^2) + deinv ---
__global__ void __launch_bounds__(256, 4)
prep_fs(const float* __restrict__ F, const float* __restrict__ Dv,
        const float* __restrict__ De, int Nn, int Ee) {
    __shared__ float dvis[64];
    __shared__ float red[256];
    const int t = threadIdx.x;
    const int n0 = blockIdx.x * 64;
    if (t < 64) {
        int n = n0 + t;
        dvis[t] = (n < Nn) ? rsqrtf(Dv[(size_t)n * Nn + n] + EPSF) : 0.f;
    }
    if (blockIdx.x < 20) {
        int e = blockIdx.x * 256 + t;
        g_deinv[e] = (e < Ee) ? 1.f / (De[(size_t)e * Ee + e] + EPSF) : 0.f;
    }
    __syncthreads();
    float f2 = 0.f;
    #pragma unroll
    for (int i = 0; i < 8; ++i) {
        int g = t + 256 * i;             // 2048 float4 slots (64 n x 32)
        int nl = g >> 5;
        int d4 = (g & 31) * 4;
        int n = n0 + nl;
        if (n < Nn) {
            float4 v = *(const float4*)&F[(size_t)n * DD + d4];
            f2 += v.x * v.x + v.y * v.y + v.z * v.z + v.w * v.w;
            float sc = dvis[nl];
            __nv_bfloat162 p0 = __floats2bfloat162_rn(v.x * sc, v.y * sc);
            __nv_bfloat162 p1 = __floats2bfloat162_rn(v.z * sc, v.w * sc);
            *(uint2*)&g_Fs[(size_t)n * DD + d4] =
                make_uint2(*(uint32_t*)&p0, *(uint32_t*)&p1);
        }
    }
    red[t] = f2;
    __syncthreads();
    #pragma unroll
    for (int s2 = 128; s2 > 0; s2 >>= 1) {
        if (t < s2) red[t] += red[t + s2];
        __syncthreads();
    }
    if (t == 0) g_f2sum[blockIdx.x] = red[0];
}

// ---------------- GEMM: HMMA 128d x 64e + SIMT f32x2 8e, 296 CTAs ------------
// Dyn SMEM 53248: A 2x16KB @0 ([k][d] 256B pitch, SWZ256),
//                 B 2x8KB @32768 ([k][64e] 128B pitch, SWZ),
//                 Bext 2x2KB @49152 ([k][8e] f32, no swizzle)
__global__ void __launch_bounds__(256, 2)
gemm_kernel(const float* __restrict__ H, int Nn, int Ee) {
    extern __shared__ __align__(1024) char smem[];
    const uint32_t sb = smem_u32(smem);

    const int t = threadIdx.x;
    const int lane = t & 31;
    const int wid = t >> 5;
    const int wm = wid & 3;
    const int wn = wid >> 2;
    const int m0 = wm * 32;
    const int n0w = wn * 32;

    // work mapping: 16 tiles x 5 slices + 54 tiles x 4 slices = 296
    const int bid = blockIdx.x;
    int et, sl, nsl;
    if (bid < 80) { et = bid / 5;  sl = bid % 5; nsl = 5; }
    else { int r = bid - 80; et = 16 + (r >> 2); sl = r & 3; nsl = 4; }
    const int e0 = et * ETILE;
    const int c0 = (sl * NCHUNKS) / nsl;
    const int c1 = ((sl + 1) * NCHUNKS) / nsl;
    const int nch = c1 - c0;
    const bool tailB = (e0 + 64 > Ee);
    const bool tailX = (e0 + ETILE > Ee);

    const int krow = t >> 2;             // 0..63 for B LDG/STS
    const int ecol = (t & 3) * 16;

    float acc[2][4][4];
    #pragma unroll
    for (int i = 0; i < 2; ++i)
        #pragma unroll
        for (int j = 0; j < 4; ++j)
            #pragma unroll
            for (int q = 0; q < 4; ++q) acc[i][j][q] = 0.f;

    ull xacc0 = 0, xacc1 = 0;            // SIMT accs: (d0,d1) for e_even/e_odd

    const int aKr = (lane & 15);         // A ldsm: k row
    const int aMc = (lane >> 4) * 8;     // A ldsm: m col group
    const int bKr = (lane & 15);
    const int bNc = (lane >> 4) * 8;

    // SIMT lane mapping: dg = lane&7 (d-pair), eg = lane>>3 (e-pair)
    const uint32_t aoffS = (uint32_t)((wid * 16 + (lane & 7) * 2) * 2);
    const uint32_t boffS = (uint32_t)((lane >> 3) * 8);

    uint32_t w[8];                       // B staging (bf16x2)
    float4 xv;                           // Bext staging

#define LOAD_A(buf, chunk) do {                                              \
        int _cg = (chunk);                                                   \
        _Pragma("unroll")                                                    \
        for (int _i = 0; _i < 4; ++_i) {                                     \
            int pos = t + 256 * _i;                                          \
            int row = pos >> 4;                                              \
            int c16 = pos & 15;                                              \
            const __nv_bfloat16* src =                                       \
                &g_Fs[(size_t)(_cg * 64 + row) * DD + c16 * 8];              \
            uint32_t off = (uint32_t)(row * 256 + c16 * 16);                 \
            CPA16((buf) + SWZ256(off), src);                                 \
        }                                                                    \
    } while (0)

#define LDG_H(chunk) do {                                                    \
        int _n = (chunk) * 64 + krow;                                        \
        bool _v = _n < Nn;                                                   \
        const float* _hr = H + (size_t)_n * Ee;                              \
        _Pragma("unroll")                                                    \
        for (int _j = 0; _j < 4; ++_j) {                                     \
            float4 f;                                                        \
            if (!tailB) {                                                    \
                f = _v ? *(const float4*)&_hr[e0 + ecol + 4 * _j]            \
                       : make_float4(0.f, 0.f, 0.f, 0.f);                    \
            } else {                                                         \
                int _e = e0 + ecol + 4 * _j;                                 \
                f.x = (_v && _e + 0 < Ee) ? _hr[_e + 0] : 0.f;               \
                f.y = (_v && _e + 1 < Ee) ? _hr[_e + 1] : 0.f;               \
                f.z = (_v && _e + 2 < Ee) ? _hr[_e + 2] : 0.f;               \
                f.w = (_v && _e + 3 < Ee) ? _hr[_e + 3] : 0.f;               \
            }                                                                \
            __nv_bfloat162 p0 = __floats2bfloat162_rn(f.x, f.y);             \
            __nv_bfloat162 p1 = __floats2bfloat162_rn(f.z, f.w);             \
            w[2 * _j]     = *(uint32_t*)&p0;                                 \
            w[2 * _j + 1] = *(uint32_t*)&p1;                                 \
        }                                                                    \
    } while (0)

#define LDG_X(chunk) do {                                                    \
        if (t < 128) {                                                       \
            int _n = (chunk) * 64 + (t >> 1);                                \
            int _e = e0 + 64 + (t & 1) * 4;                                  \
            xv = make_float4(0.f, 0.f, 0.f, 0.f);                            \
            if (_n < Nn) {                                                   \
                const float* _hr = H + (size_t)_n * Ee;                      \
                if (!tailX) xv = *(const float4*)&_hr[_e];                   \
                else {                                                       \
                    if (_e + 0 < Ee) xv.x = _hr[_e + 0];                     \
                    if (_e + 1 < Ee) xv.y = _hr[_e + 1];                     \
                    if (_e + 2 < Ee) xv.z = _hr[_e + 2];                     \
                    if (_e + 3 < Ee) xv.w = _hr[_e + 3];                     \
                }                                                            \
            }                                                                \
        }                                                                    \
    } while (0)

#define STS_H(buf) do {                                                      \
        uint32_t off = (uint32_t)(krow * 128 + ecol * 2);                    \
        sts128((buf) + SWZ(off),      w[0], w[1], w[2], w[3]);               \
        sts128((buf) + SWZ(off + 16), w[4], w[5], w[6], w[7]);               \
    } while (0)

#define STS_X(buf) do {                                                      \
        if (t < 128) {                                                       \
            uint32_t off = (uint32_t)((t >> 1) * 32 + (t & 1) * 16);         \
            sts128((buf) + off, __float_as_uint(xv.x), __float_as_uint(xv.y),\
                   __float_as_uint(xv.z), __float_as_uint(xv.w));            \
        }                                                                    \
    } while (0)

#define COMPUTE(abuf, bbuf) do {                                             \
        _Pragma("unroll")                                                    \
        for (int k0 = 0; k0 < 64; k0 += 16) {                                \
            uint32_t afr[2][4];                                              \
            _Pragma("unroll")                                                \
            for (int i = 0; i < 2; ++i) {                                    \
                uint32_t off = (uint32_t)((k0 + aKr) * 256                   \
                                          + (m0 + i * 16 + aMc) * 2);        \
                LDSM4T_A(afr[i], (abuf) + SWZ256(off));                      \
            }                                                                \
            uint32_t bfr[2][4];                                              \
            _Pragma("unroll")                                                \
            for (int jb = 0; jb < 2; ++jb) {                                 \
                uint32_t off = (uint32_t)((k0 + bKr) * 128                   \
                                          + (n0w + jb * 16 + bNc) * 2);      \
                LDSM4T(bfr[jb], (bbuf) + SWZ(off));                          \
            }                                                                \
            _Pragma("unroll")                                                \
            for (int i = 0; i < 2; ++i)                                      \
                _Pragma("unroll")                                            \
                for (int j = 0; j < 4; ++j)                                  \
                    mma16816(acc[i][j], afr[i],                              \
                             bfr[j >> 1][(j & 1) * 2],                       \
                             bfr[j >> 1][(j & 1) * 2 + 1]);                  \
        }                                                                    \
    } while (0)

#define SIMT_COMPUTE(abuf, xbuf) do {                                        \
        _Pragma("unroll 8")                                                  \
        for (int k = 0; k < 64; ++k) {                                       \
            uint32_t ra, bx, by;                                             \
            uint32_t aaddr = (abuf) + SWZ256((uint32_t)(k * 256) + aoffS);   \
            asm volatile("ld.shared.b32 %0, [%1];" : "=r"(ra) : "r"(aaddr)); \
            uint32_t baddr = (xbuf) + (uint32_t)(k * 32) + boffS;            \
            asm volatile("ld.shared.v2.b32 {%0,%1}, [%2];"                   \
                         : "=r"(bx), "=r"(by) : "r"(baddr));                 \
            ull av = pack2u(ra << 16, ra & 0xffff0000u);                     \
            xacc0 = ffma2(av, pack2u(bx, bx), xacc0);                        \
            xacc1 = ffma2(av, pack2u(by, by), xacc1);                        \
        }                                                                    \
    } while (0)

    // ---- pipeline ----
    LOAD_A(sb, c0);
    CPA_COMMIT();
    LDG_H(c0);
    LDG_X(c0);
    CPA_WAIT0();
    STS_H(sb + 32768);
    STS_X(sb + 49152);
    __syncthreads();

    for (int cc = 0; cc < nch; ++cc) {
        const int b = cc & 1;
        const uint32_t aCur = sb + b * 16384;
        const uint32_t bCur = sb + 32768 + b * 8192;
        const uint32_t xCur = sb + 49152 + b * 2048;
        const uint32_t aNxt = sb + (b ^ 1) * 16384;
        const uint32_t bNxt = sb + 32768 + (b ^ 1) * 8192;
        const uint32_t xNxt = sb + 49152 + (b ^ 1) * 2048;
        const bool has = (cc + 1) < nch;
        if (has) {
            LOAD_A(aNxt, c0 + cc + 1);
            CPA_COMMIT();
            LDG_H(c0 + cc + 1);
            LDG_X(c0 + cc + 1);
        }
        COMPUTE(aCur, bCur);
        SIMT_COMPUTE(aCur, xCur);
        if (has) {
            CPA_WAIT0();
            STS_H(bNxt);
            STS_X(xNxt);
        }
        __syncthreads();
    }

    // ---- write HMMA partials: g_Mpart[sl][d][e] ----
    #pragma unroll
    for (int i = 0; i < 2; ++i) {
        #pragma unroll
        for (int j = 0; j < 4; ++j) {
            int d = m0 + i * 16 + (lane >> 2);
            int e = e0 + n0w + j * 8 + (lane & 3) * 2;
            size_t base = ((size_t)(sl * DD + d)) * EPITCH + e;
            *(float2*)&g_Mpart[base] = make_float2(acc[i][j][0], acc[i][j][1]);
            *(float2*)&g_Mpart[base + (size_t)8 * EPITCH] =
                make_float2(acc[i][j][2], acc[i][j][3]);
        }
    }
    // ---- write SIMT partials ----
    {
        int d0 = wid * 16 + (lane & 7) * 2;
        int e  = e0 + 64 + (lane >> 3) * 2;
        float x0, y0, x1, y1;
        unpack2f(xacc0, x0, y0);
        unpack2f(xacc1, x1, y1);
        size_t r0 = ((size_t)(sl * DD + d0)) * EPITCH;
        size_t r1 = ((size_t)(sl * DD + d0 + 1)) * EPITCH;
        g_Mpart[r0 + e]     = x0;
        g_Mpart[r1 + e]     = y0;
        g_Mpart[r0 + e + 1] = x1;
        g_Mpart[r1 + e + 1] = y1;
    }
}

// ---------------- pass 3 + fused final reduce --------------------------------
__global__ void __launch_bounds__(256, 8)
pass3_kernel(float* __restrict__ out, int Nn, int nprep) {
    __shared__ float r[256];
    __shared__ int isLast;
    const int t = threadIdx.x;
    const int d = blockIdx.x / 20;
    const int e = (blockIdx.x % 20) * 256 + t;
    const int nsl = ((e / ETILE) < 16) ? 5 : 4;
    float v = 0.f;
    #pragma unroll
    for (int j = 0; j < NSLMAX; ++j)
        if (j < nsl) v += g_Mpart[((size_t)(j * DD + d)) * EPITCH + e];
    r[t] = v * v * g_deinv[e];
    __syncthreads();
    #pragma unroll
    for (int s = 128; s > 0; s >>= 1) {
        if (t < s) r[t] += r[t + s];
        __syncthreads();
    }
    if (t == 0) {
        g_blocksum[blockIdx.x] = r[0];
        __threadfence();
        int done = atomicAdd(&g_count, 1);
        isLast = (done == (int)gridDim.x - 1);
    }
    __syncthreads();
    if (isLast) {
        float acc = 0.f;
        for (int i = t; i < nprep; i += 256) acc += g_f2sum[i];
        for (int i = t; i < 2560; i += 256) acc -= g_blocksum[i];
        r[t] = acc;
        __syncthreads();
        #pragma unroll
        for (int s = 128; s > 0; s >>= 1) {
            if (t < s) r[t] += r[t + s];
            __syncthreads();
        }
        if (t == 0) {
            out[0] = r[0] / (float)Nn;
            g_count = 0;
        }
    }
}

// ---------------- launch ------------------------------------------------------
extern "C" void kernel_launch(void* const* d_in, const int* in_sizes, int n_in,
                              void* d_out, int out_size) {
    const float* F  = (const float*)d_in[0];   // [N,128]
    const float* H  = (const float*)d_in[1];   // [N,E]
    const float* Dv = (const float*)d_in[2];   // [N,N]
    const float* De = (const float*)d_in[3];   // [E,E]
    float* out = (float*)d_out;

    int Nn = in_sizes[0] / DD;                 // 10000
    int Ee = in_sizes[1] / Nn;                 // 5000
    int etiles = (Ee + ETILE - 1) / ETILE;     // 70
    int nblocks = 16 * 5 + (etiles - 16) * 4;  // 296
    int nprep = NCHUNKS;                       // 157 prep blocks (64 rows each)

    cudaFuncSetAttribute(gemm_kernel, cudaFuncAttributeMaxDynamicSharedMemorySize,
                         53248);

    prep_fs<<<nprep, 256>>>(F, Dv, De, Nn, Ee);
    gemm_kernel<<<nblocks, 256, 53248>>>(H, Nn, Ee);
    pass3_kernel<<<2560, 256>>>(out, Nn, nprep);
}

// round 8
// speedup vs baseline: 1.5022x; 1.4367x over previous
#include <cuda_runtime.h>
#include <cuda_bf16.h>
#include <stdint.h>
#include <math.h>

#define EPSF 1e-8f
#define DD 128               // d
#define KPAD 10048           // 314*32 padded K (= problem N)
#define NCHUNKS 157          // 64-k chunks
#define EPAD 5120
#define EPITCH 5120          // 40*128
#define NKS 7                // K splits

// ---------------- static device scratch (no allocation) ----------------------
static __device__ __align__(256) __nv_bfloat16 g_FsT[DD * KPAD];     // Fs^T K-major bf16
static __device__ __align__(256) float g_Mpart[NKS * DD * EPITCH];   // 18.35 MB partials
static __device__ float g_deinv[EPAD];
static __device__ float g_blocksum[2560];
static __device__ float g_f2sum[320];
static __device__ int   g_count;

// ---------------- helpers ----------------------------------------------------
__device__ __forceinline__ uint32_t smem_u32(const void* p) {
    uint32_t a;
    asm("{ .reg .u64 t; cvta.to.shared.u64 t, %1; cvt.u32.u64 %0, t; }"
        : "=r"(a) : "l"(p));
    return a;
}
#define SWZ(o) ((o) ^ (((o) >> 3) & 0x70))

__device__ __forceinline__ void sts128(uint32_t addr, uint32_t a, uint32_t b,
                                       uint32_t c, uint32_t d) {
    asm volatile("st.shared.v4.b32 [%0], {%1,%2,%3,%4};"
                 :: "r"(addr), "r"(a), "r"(b), "r"(c), "r"(d) : "memory");
}
#define CPA16(dst, src) \
    asm volatile("cp.async.ca.shared.global [%0], [%1], 16;" \
                 :: "r"(dst), "l"(src) : "memory")
#define CPA_COMMIT() asm volatile("cp.async.commit_group;" ::: "memory")
#define CPA_WAIT0()  asm volatile("cp.async.wait_group 0;" ::: "memory")

#define LDSM4(r, addr) \
    asm volatile("ldmatrix.sync.aligned.m8n8.x4.shared.b16 {%0,%1,%2,%3}, [%4];" \
                 : "=r"((r)[0]), "=r"((r)[1]), "=r"((r)[2]), "=r"((r)[3]) : "r"(addr))
#define LDSM4T(r, addr) \
    asm volatile("ldmatrix.sync.aligned.m8n8.x4.trans.shared.b16 {%0,%1,%2,%3}, [%4];" \
                 : "=r"((r)[0]), "=r"((r)[1]), "=r"((r)[2]), "=r"((r)[3]) : "r"(addr))

__device__ __forceinline__ void mma16816(float* c, const uint32_t* a,
                                         uint32_t b0, uint32_t b1) {
    asm volatile(
        "mma.sync.aligned.m16n8k16.row.col.f32.bf16.bf16.f32 "
        "{%0,%1,%2,%3}, {%4,%5,%6,%7}, {%8,%9}, {%0,%1,%2,%3};"
        : "+f"(c[0]), "+f"(c[1]), "+f"(c[2]), "+f"(c[3])
        : "r"(a[0]), "r"(a[1]), "r"(a[2]), "r"(a[3]), "r"(b0), "r"(b1));
}

// ---------------- prep: FsT (bf16 transpose, 32 rows/blk) + sum(F^2) + diag --
__global__ void __launch_bounds__(256, 4)
prep_fst(const float* __restrict__ F, const float* __restrict__ Dv,
         const float* __restrict__ De, int Nn, int Ee) {
    __shared__ __nv_bfloat16 s[32][132];
    __shared__ float red[256];
    __shared__ float dvis[32];
    const int t = threadIdx.x;
    const int n0 = blockIdx.x * 32;

    if (t < 32) {
        int n = n0 + t;
        dvis[t] = (n < Nn) ? rsqrtf(Dv[(size_t)n * Nn + n] + EPSF) : 0.f;
    }
    // fused deinv fill (first 20 blocks)
    if (blockIdx.x < 20) {
        int e = blockIdx.x * 256 + t;
        g_deinv[e] = (e < Ee) ? 1.f / (De[(size_t)e * Ee + e] + EPSF) : 0.f;
    }
    __syncthreads();

    float f2 = 0.f;
    #pragma unroll
    for (int i = 0; i < 4; ++i) {
        int g = t + 256 * i;          // 1024 float4 slots (32 n x 32)
        int nl = g >> 5;
        int d4 = (g & 31) * 4;
        int n = n0 + nl;
        float4 v = make_float4(0.f, 0.f, 0.f, 0.f);
        float sc = 0.f;
        if (n < Nn) { v = *(const float4*)&F[(size_t)n * DD + d4]; sc = dvis[nl]; }
        f2 += v.x * v.x + v.y * v.y + v.z * v.z + v.w * v.w;
        s[nl][d4 + 0] = __float2bfloat16(v.x * sc);
        s[nl][d4 + 1] = __float2bfloat16(v.y * sc);
        s[nl][d4 + 2] = __float2bfloat16(v.z * sc);
        s[nl][d4 + 3] = __float2bfloat16(v.w * sc);
    }
    __syncthreads();
    {   // transposed write: thread -> (d = t>>1, 16 n values) = 2 x uint4
        int d = t >> 1;
        int nh = (t & 1) * 16;
        uint32_t w[8];
        #pragma unroll
        for (int j = 0; j < 8; ++j) {
            __nv_bfloat162 p;
            p.x = s[nh + 2 * j][d];
            p.y = s[nh + 2 * j + 1][d];
            w[j] = *(uint32_t*)&p;
        }
        uint4* dst = (uint4*)&g_FsT[(size_t)d * KPAD + n0 + nh];
        dst[0] = make_uint4(w[0], w[1], w[2], w[3]);
        dst[1] = make_uint4(w[4], w[5], w[6], w[7]);
    }
    red[t] = f2;
    __syncthreads();
    #pragma unroll
    for (int s2 = 128; s2 > 0; s2 >>= 1) {
        if (t < s2) red[t] += red[t + s2];
        __syncthreads();
    }
    if (t == 0) g_f2sum[blockIdx.x] = red[0];
}

// ---------------- GEMM: mma.sync bf16, CTA tile 128(d) x 128(e), K-split -----
// (R4 verbatim) Dynamic SMEM 64KB: A 2x16KB @0, B 2x16KB @32768 (lo/hi 8KB).
__global__ void __launch_bounds__(256, 2)
gemm_kernel(const float* __restrict__ H, int Nn, int Ee) {
    extern __shared__ __align__(1024) char smem[];
    const uint32_t sb = smem_u32(smem);

    const int t = threadIdx.x;
    const int lane = t & 31;
    const int wid = t >> 5;
    const int wm = wid & 3;            // 4 m-warps
    const int wn = wid >> 2;           // 2 n-warps (64 e each)
    const int m0 = wm * 32;

    const int e0 = blockIdx.x * 128;
    const int ks = blockIdx.y;
    const int c0 = (ks * NCHUNKS) / NKS;
    const int c1 = ((ks + 1) * NCHUNKS) / NKS;
    const int nch = c1 - c0;
    const bool tail = (e0 + 128 > Ee);

    const int krow = t >> 2;           // 0..63
    const int ecol = (t & 3) * 32;     // 32 e per thread
    const int eloc = ecol & 63;

    float acc[2][8][4];
    #pragma unroll
    for (int i = 0; i < 2; ++i)
        #pragma unroll
        for (int j = 0; j < 8; ++j)
            #pragma unroll
            for (int q = 0; q < 4; ++q) acc[i][j][q] = 0.f;

    const int aRow = (lane & 15);
    const int aKh  = (lane >> 4) * 8;
    const int bKr  = (lane & 15);
    const int bNc  = (lane >> 4) * 8;

    uint32_t w[16];                    // converted B staging (bf16x2)

#define LOAD_A(buf, chunk) do {                                              \
        int _cg = (chunk);                                                   \
        _Pragma("unroll")                                                    \
        for (int _i = 0; _i < 4; ++_i) {                                     \
            int pos = t + 256 * _i;                                          \
            int row = pos >> 3;                                              \
            int cc  = pos & 7;                                               \
            const __nv_bfloat16* src = &g_FsT[(size_t)row * KPAD + _cg * 64 + cc * 8]; \
            uint32_t off = (uint32_t)(row * 128 + cc * 16);                  \
            CPA16((buf) + SWZ(off), src);                                    \
        }                                                                    \
    } while (0)

#define LDG_H(chunk) do {                                                    \
        int _n = (chunk) * 64 + krow;                                        \
        bool _v = _n < Nn;                                                   \
        const float* _hr = H + (size_t)_n * Ee;                              \
        _Pragma("unroll")                                                    \
        for (int _j = 0; _j < 8; ++_j) {                                     \
            float4 f;                                                        \
            if (!tail) {                                                     \
                f = _v ? *(const float4*)&_hr[e0 + ecol + 4 * _j]            \
                       : make_float4(0.f, 0.f, 0.f, 0.f);                    \
            } else {                                                         \
                int _e = e0 + ecol + 4 * _j;                                 \
                f.x = (_v && _e + 0 < Ee) ? _hr[_e + 0] : 0.f;               \
                f.y = (_v && _e + 1 < Ee) ? _hr[_e + 1] : 0.f;               \
                f.z = (_v && _e + 2 < Ee) ? _hr[_e + 2] : 0.f;               \
                f.w = (_v && _e + 3 < Ee) ? _hr[_e + 3] : 0.f;               \
            }                                                                \
            __nv_bfloat162 p0 = __floats2bfloat162_rn(f.x, f.y);             \
            __nv_bfloat162 p1 = __floats2bfloat162_rn(f.z, f.w);             \
            w[2 * _j]     = *(uint32_t*)&p0;                                 \
            w[2 * _j + 1] = *(uint32_t*)&p1;                                 \
        }                                                                    \
    } while (0)

#define STS_H(bbase) do {                                                    \
        uint32_t reg = (bbase) + ((t & 2) ? 8192u : 0u);                     \
        uint32_t off = (uint32_t)(krow * 128 + eloc * 2);                    \
        sts128(reg + SWZ(off),      w[0],  w[1],  w[2],  w[3]);              \
        sts128(reg + SWZ(off + 16), w[4],  w[5],  w[6],  w[7]);              \
        sts128(reg + SWZ(off + 32), w[8],  w[9],  w[10], w[11]);             \
        sts128(reg + SWZ(off + 48), w[12], w[13], w[14], w[15]);             \
    } while (0)

#define COMPUTE(abuf, bbase) do {                                            \
        uint32_t breg = (bbase) + (wn ? 8192u : 0u);                         \
        _Pragma("unroll")                                                    \
        for (int k0 = 0; k0 < 64; k0 += 16) {                                \
            uint32_t afr[2][4];                                              \
            _Pragma("unroll")                                                \
            for (int i = 0; i < 2; ++i) {                                    \
                uint32_t off = (uint32_t)((m0 + i * 16 + aRow) * 128         \
                                          + (k0 + aKh) * 2);                 \
                LDSM4(afr[i], (abuf) + SWZ(off));                            \
            }                                                                \
            uint32_t bfr[4][4];                                              \
            _Pragma("unroll")                                                \
            for (int jb = 0; jb < 4; ++jb) {                                 \
                uint32_t off = (uint32_t)((k0 + bKr) * 128                   \
                                          + (jb * 16 + bNc) * 2);            \
                LDSM4T(bfr[jb], breg + SWZ(off));                            \
            }                                                                \
            _Pragma("unroll")                                                \
            for (int i = 0; i < 2; ++i)                                      \
                _Pragma("unroll")                                            \
                for (int j = 0; j < 8; ++j)                                  \
                    mma16816(acc[i][j], afr[i],                              \
                             bfr[j >> 1][(j & 1) * 2],                       \
                             bfr[j >> 1][(j & 1) * 2 + 1]);                  \
        }                                                                    \
    } while (0)

    // ---- pipeline (double-buffered) ----
    LOAD_A(sb, c0);
    CPA_COMMIT();
    LDG_H(c0);
    CPA_WAIT0();
    STS_H(sb + 32768);
    __syncthreads();

    for (int cc = 0; cc < nch; ++cc) {
        const int b = cc & 1;
        const uint32_t aCur = sb + b * 16384;
        const uint32_t bCur = sb + 32768 + b * 16384;
        const uint32_t aNxt = sb + (b ^ 1) * 16384;
        const uint32_t bNxt = sb + 32768 + (b ^ 1) * 16384;
        const bool has = (cc + 1) < nch;
        if (has) {
            LOAD_A(aNxt, c0 + cc + 1);
            CPA_COMMIT();
            LDG_H(c0 + cc + 1);
        }
        COMPUTE(aCur, bCur);
        if (has) {
            CPA_WAIT0();
            STS_H(bNxt);
        }
        __syncthreads();
    }

    // ---- write partials: g_Mpart[ks][d][e] ----
    const int wn64 = wn * 64;
    #pragma unroll
    for (int i = 0; i < 2; ++i) {
        #pragma unroll
        for (int j = 0; j < 8; ++j) {
            int d = m0 + i * 16 + (lane >> 2);
            int e = e0 + wn64 + j * 8 + (lane & 3) * 2;
            size_t base = ((size_t)(ks * DD + d)) * EPITCH + e;
            *(float2*)&g_Mpart[base] = make_float2(acc[i][j][0], acc[i][j][1]);
            *(float2*)&g_Mpart[base + (size_t)8 * EPITCH] =
                make_float2(acc[i][j][2], acc[i][j][3]);
        }
    }
}

// ---------------- pass 3 + fused final reduce --------------------------------
// grid 2560: d = bid/20, e = (bid%20)*256 + t. Last block does the final sum.
__global__ void __launch_bounds__(256, 8)
pass3_kernel(float* __restrict__ out, int Nn, int nprep) {
    __shared__ float r[256];
    __shared__ int isLast;
    const int t = threadIdx.x;
    const int d = blockIdx.x / 20;
    const int e = (blockIdx.x % 20) * 256 + t;
    float v = 0.f;
    #pragma unroll
    for (int j = 0; j < NKS; ++j)
        v += g_Mpart[((size_t)(j * DD + d)) * EPITCH + e];
    r[t] = v * v * g_deinv[e];
    __syncthreads();
    #pragma unroll
    for (int s = 128; s > 0; s >>= 1) {
        if (t < s) r[t] += r[t + s];
        __syncthreads();
    }
    if (t == 0) {
        g_blocksum[blockIdx.x] = r[0];
        __threadfence();
        int done = atomicAdd(&g_count, 1);
        isLast = (done == (int)gridDim.x - 1);
    }
    __syncthreads();
    if (isLast) {
        float acc = 0.f;
        for (int i = t; i < nprep; i += 256) acc += g_f2sum[i];
        for (int i = t; i < 2560; i += 256) acc -= g_blocksum[i];
        r[t] = acc;
        __syncthreads();
        #pragma unroll
        for (int s = 128; s > 0; s >>= 1) {
            if (t < s) r[t] += r[t + s];
            __syncthreads();
        }
        if (t == 0) {
            out[0] = r[0] / (float)Nn;
            g_count = 0;               // reset for next graph replay
        }
    }
}

// ---------------- launch ------------------------------------------------------
extern "C" void kernel_launch(void* const* d_in, const int* in_sizes, int n_in,
                              void* d_out, int out_size) {
    const float* F  = (const float*)d_in[0];   // [N,128]
    const float* H  = (const float*)d_in[1];   // [N,E]
    const float* Dv = (const float*)d_in[2];   // [N,N]
    const float* De = (const float*)d_in[3];   // [E,E]
    float* out = (float*)d_out;

    int Nn = in_sizes[0] / DD;                 // 10000
    int Ee = in_sizes[1] / Nn;                 // 5000
    int etiles = (Ee + 127) / 128;             // 40
    int nprep = KPAD / 32;                     // 314

    cudaFuncSetAttribute(gemm_kernel, cudaFuncAttributeMaxDynamicSharedMemorySize,
                         65536);

    prep_fst<<<nprep, 256>>>(F, Dv, De, Nn, Ee);
    gemm_kernel<<<dim3(etiles, NKS), 256, 65536>>>(H, Nn, Ee);
    pass3_kernel<<<2560, 256>>>(out, Nn, nprep);
}